// round 16
// baseline (speedup 1.0000x reference)
#include <cuda_runtime.h>
#include <cuda_bf16.h>
#include <math_constants.h>

// Problem constants
#define NPIX 2304          // 48*48
#define NPIX2 1152         // NPIX/2
#define CIN  256
#define HID  128
#define NHEADS 4
#define DHEAD 32
#define BATCH 8
#define QSCALE 0.17677669529663687f   // 1/sqrt(32)

// Pre-split bf16 planes (hi/lo), materialized once by producer epilogues:
//   Q,K : ushort [bh][n][32]        (dim-contiguous; uint read = dim pair)
//   V   : uint   [bh*32+d][n2]      (uint = key pair (2n,2n+1) at dim d)
//   O   : uint   [b*64+c2][n]       (uint = dim pair (2c,2c+1) at pixel n)
__device__ unsigned short g_qh[BATCH * NHEADS * NPIX * 32];
__device__ unsigned short g_ql[BATCH * NHEADS * NPIX * 32];
__device__ unsigned short g_kh[BATCH * NHEADS * NPIX * 32];
__device__ unsigned short g_kl[BATCH * NHEADS * NPIX * 32];
__device__ unsigned g_vh[BATCH * NHEADS * 32 * NPIX2];
__device__ unsigned g_vl[BATCH * NHEADS * 32 * NPIX2];
__device__ unsigned g_oh[BATCH * 64 * NPIX];
__device__ unsigned g_ol[BATCH * 64 * NPIX];

// ---------------------------------------------------------------------------
// Helpers
// ---------------------------------------------------------------------------
__device__ __forceinline__ unsigned pack_bf16(float lo, float hi)
{
    unsigned r;
    asm("cvt.rn.bf16x2.f32 %0, %1, %2;" : "=r"(r) : "f"(hi), "f"(lo));
    return r;   // low 16 bits = lo element
}

__device__ __forceinline__ void split2_bf16(float v0, float v1,
                                            unsigned& h, unsigned& l)
{
    h = pack_bf16(v0, v1);
    float h0 = __uint_as_float(h << 16);
    float h1 = __uint_as_float(h & 0xffff0000u);
    l = pack_bf16(v0 - h0, v1 - h1);
}

__device__ __forceinline__ void mma_bf16(float d[4], const unsigned a[4],
                                         unsigned b0, unsigned b1)
{
    asm volatile(
        "mma.sync.aligned.m16n8k16.row.col.f32.bf16.bf16.f32 "
        "{%0,%1,%2,%3}, {%4,%5,%6,%7}, {%8,%9}, {%0,%1,%2,%3};\n"
        : "+f"(d[0]), "+f"(d[1]), "+f"(d[2]), "+f"(d[3])
        : "r"(a[0]), "r"(a[1]), "r"(a[2]), "r"(a[3]), "r"(b0), "r"(b1));
}

__device__ __forceinline__ float rmax4(float v) {
    v = fmaxf(v, __shfl_xor_sync(0xffffffffu, v, 1));
    v = fmaxf(v, __shfl_xor_sync(0xffffffffu, v, 2));
    return v;
}
__device__ __forceinline__ float rsum4(float v) {
    v += __shfl_xor_sync(0xffffffffu, v, 1);
    v += __shfl_xor_sync(0xffffffffu, v, 2);
    return v;
}

#define WST2 12
#define NST2 72

// ---------------------------------------------------------------------------
// Kernel 1: QKV projection, bf16x3 mma.  Epilogue writes pre-split planes.
// ---------------------------------------------------------------------------
__global__ void __launch_bounds__(128) qkv_mma_kernel(const float* __restrict__ x,
                                                      const float* __restrict__ w)
{
    __shared__ __align__(16) unsigned Wh2[128 * WST2], Wl2[128 * WST2];
    __shared__ __align__(16) unsigned Xh2[8 * NST2],  Xl2[8 * NST2];

    const int b  = blockIdx.z;
    const int ob = blockIdx.y * 128;
    const int nb = blockIdx.x * 64;
    const int tid  = threadIdx.x;
    const int warp = tid >> 5;
    const int lane = tid & 31;
    const int g = lane >> 2, t = lane & 3;

    const float* xb = x + (size_t)b * CIN * NPIX;

    float acc[2][8][4] = {};

    for (int kb = 0; kb < CIN; kb += 16) {
        __syncthreads();
        #pragma unroll
        for (int j = 0; j < 4; j++) {
            int i = tid + j * 128;
            int o = i >> 2, k4 = (i & 3) * 4;
            float4 wv = *(const float4*)&w[(ob + o) * CIN + kb + k4];
            unsigned h0, l0, h1, l1;
            split2_bf16(wv.x, wv.y, h0, l0);
            split2_bf16(wv.z, wv.w, h1, l1);
            *(uint2*)&Wh2[o * WST2 + k4 / 2] = make_uint2(h0, h1);
            *(uint2*)&Wl2[o * WST2 + k4 / 2] = make_uint2(l0, l1);
        }
        #pragma unroll
        for (int s = 0; s < 4; s++) {
            int i = tid + s * 128;
            int n = i & 63, k2 = i >> 6;
            const float* base = &xb[(size_t)(kb + 2 * k2) * NPIX + nb + n];
            unsigned h, l;
            split2_bf16(base[0], base[NPIX], h, l);
            Xh2[k2 * NST2 + n] = h;
            Xl2[k2 * NST2 + n] = l;
        }
        __syncthreads();

        unsigned ah[2][4], al[2][4];
        #pragma unroll
        for (int mf = 0; mf < 2; mf++) {
            const int wo = warp * 32 + mf * 16;
            ah[mf][0] = Wh2[(wo + g)     * WST2 + t];     al[mf][0] = Wl2[(wo + g)     * WST2 + t];
            ah[mf][1] = Wh2[(wo + 8 + g) * WST2 + t];     al[mf][1] = Wl2[(wo + 8 + g) * WST2 + t];
            ah[mf][2] = Wh2[(wo + g)     * WST2 + t + 4]; al[mf][2] = Wl2[(wo + g)     * WST2 + t + 4];
            ah[mf][3] = Wh2[(wo + 8 + g) * WST2 + t + 4]; al[mf][3] = Wl2[(wo + 8 + g) * WST2 + t + 4];
        }
        #pragma unroll
        for (int nt = 0; nt < 8; nt++) {
            unsigned b0h = Xh2[t       * NST2 + nt * 8 + g];
            unsigned b1h = Xh2[(t + 4) * NST2 + nt * 8 + g];
            unsigned b0l = Xl2[t       * NST2 + nt * 8 + g];
            unsigned b1l = Xl2[(t + 4) * NST2 + nt * 8 + g];
            mma_bf16(acc[0][nt], ah[0], b0h, b1h);
            mma_bf16(acc[0][nt], ah[0], b0l, b1l);
            mma_bf16(acc[0][nt], al[0], b0h, b1h);
            mma_bf16(acc[1][nt], ah[1], b0h, b1h);
            mma_bf16(acc[1][nt], ah[1], b0l, b1l);
            mma_bf16(acc[1][nt], al[1], b0h, b1h);
        }
    }

    // Epilogue -> pre-split planes.  sec uniform per block.
    const int sec = ob >> 7;   // 0=q, 1=k, 2=v
    #pragma unroll
    for (int mf = 0; mf < 2; mf++) {
        #pragma unroll
        for (int r = 0; r < 2; r++) {
            int o  = ob + warp * 32 + mf * 16 + r * 8 + g;
            int oc = o & 127;
            int bh = b * NHEADS + (oc >> 5);
            int d  = oc & 31;
            if (sec == 2) {
                unsigned* vh = g_vh + (size_t)(bh * 32 + d) * NPIX2;
                unsigned* vl = g_vl + (size_t)(bh * 32 + d) * NPIX2;
                #pragma unroll
                for (int nt = 0; nt < 8; nt++) {
                    int n0 = nb + nt * 8 + 2 * t;
                    unsigned h, l;
                    split2_bf16(acc[mf][nt][2 * r], acc[mf][nt][2 * r + 1], h, l);
                    vh[n0 / 2] = h;
                    vl[n0 / 2] = l;
                }
            } else {
                const float mult = (sec == 0) ? QSCALE : 1.0f;
                unsigned short* dh = ((sec == 0) ? g_qh : g_kh) + (size_t)bh * NPIX * 32 + d;
                unsigned short* dl = ((sec == 0) ? g_ql : g_kl) + (size_t)bh * NPIX * 32 + d;
                #pragma unroll
                for (int nt = 0; nt < 8; nt++) {
                    int n0 = nb + nt * 8 + 2 * t;
                    unsigned h, l;
                    split2_bf16(acc[mf][nt][2 * r] * mult,
                                acc[mf][nt][2 * r + 1] * mult, h, l);
                    dh[(size_t)n0 * 32]       = (unsigned short)h;
                    dh[(size_t)(n0 + 1) * 32] = (unsigned short)(h >> 16);
                    dl[(size_t)n0 * 32]       = (unsigned short)l;
                    dl[(size_t)(n0 + 1) * 32] = (unsigned short)(l >> 16);
                }
            }
        }
    }
}

// ---------------------------------------------------------------------------
// Kernel 2: flash attention, bf16x3.  All operands pre-split in gmem; tile
// loads are pure uint2 copies.  QTILE=128 (warp = 32 q), KTILE=64.
// ---------------------------------------------------------------------------
#define KTILE 64
#define QTILE 128
#define KST2  20
#define VST2  36

__global__ void __launch_bounds__(128) attn_mma_kernel()
{
    __shared__ __align__(16) unsigned Ksh[64 * KST2], Ksl[64 * KST2];
    __shared__ __align__(16) unsigned Vsh[32 * VST2], Vsl[32 * VST2];

    const int bh    = blockIdx.y;
    const int qbase = blockIdx.x * QTILE;
    const int tid   = threadIdx.x;
    const int warp  = tid >> 5;
    const int lane  = tid & 31;
    const int g     = lane >> 2;
    const int t     = lane & 3;

    const unsigned short* qhp = g_qh + (size_t)bh * NPIX * 32;
    const unsigned short* qlp = g_ql + (size_t)bh * NPIX * 32;
    const unsigned short* khp = g_kh + (size_t)bh * NPIX * 32;
    const unsigned short* klp = g_kl + (size_t)bh * NPIX * 32;
    const unsigned* vhp = g_vh + (size_t)bh * 32 * NPIX2;
    const unsigned* vlp = g_vl + (size_t)bh * 32 * NPIX2;

    // Resident Q A-fragments: direct uint reads of pre-split planes
    unsigned qh[2][2][4], ql[2][2][4];
    const int qrow0 = qbase + warp * 32 + g;
    #pragma unroll
    for (int mf = 0; mf < 2; mf++) {
        const int rA = qrow0 + mf * 16, rB = rA + 8;
        #pragma unroll
        for (int kf = 0; kf < 2; kf++) {
            qh[mf][kf][0] = *(const unsigned*)&qhp[(size_t)rA * 32 + 16 * kf + 2 * t];
            qh[mf][kf][1] = *(const unsigned*)&qhp[(size_t)rB * 32 + 16 * kf + 2 * t];
            qh[mf][kf][2] = *(const unsigned*)&qhp[(size_t)rA * 32 + 16 * kf + 2 * t + 8];
            qh[mf][kf][3] = *(const unsigned*)&qhp[(size_t)rB * 32 + 16 * kf + 2 * t + 8];
            ql[mf][kf][0] = *(const unsigned*)&qlp[(size_t)rA * 32 + 16 * kf + 2 * t];
            ql[mf][kf][1] = *(const unsigned*)&qlp[(size_t)rB * 32 + 16 * kf + 2 * t];
            ql[mf][kf][2] = *(const unsigned*)&qlp[(size_t)rA * 32 + 16 * kf + 2 * t + 8];
            ql[mf][kf][3] = *(const unsigned*)&qlp[(size_t)rB * 32 + 16 * kf + 2 * t + 8];
        }
    }

    float o[2][4][4] = {};
    float mst[2][2], lst[2][2];
    #pragma unroll
    for (int mf = 0; mf < 2; mf++) {
        mst[mf][0] = -CUDART_INF_F; mst[mf][1] = -CUDART_INF_F;
        lst[mf][0] = 0.f;           lst[mf][1] = 0.f;
    }

    for (int kb = 0; kb < NPIX; kb += KTILE) {
        __syncthreads();
        // K tile: pure copies (uint2 = 4 dims)
        #pragma unroll
        for (int s = 0; s < 4; s++) {
            int i = tid + s * 128;
            int j = i >> 3, d4 = (i & 7) * 4;
            *(uint2*)&Ksh[j * KST2 + d4 / 2] =
                *(const uint2*)&khp[(size_t)(kb + j) * 32 + d4];
            *(uint2*)&Ksl[j * KST2 + d4 / 2] =
                *(const uint2*)&klp[(size_t)(kb + j) * 32 + d4];
        }
        // V tile: pure copies (uint2 = 4 keys)
        #pragma unroll
        for (int s = 0; s < 4; s++) {
            int i = tid + s * 128;
            int d = i >> 4, n4 = (i & 15) * 4;
            *(uint2*)&Vsh[d * VST2 + n4 / 2] =
                *(const uint2*)&vhp[(size_t)d * NPIX2 + (kb + n4) / 2];
            *(uint2*)&Vsl[d * VST2 + n4 / 2] =
                *(const uint2*)&vlp[(size_t)d * NPIX2 + (kb + n4) / 2];
        }
        __syncthreads();

        // ---- S = Q K^T (32 x 64 per warp), bf16x3 ----
        float s[2][8][4];
        #pragma unroll
        for (int mf = 0; mf < 2; mf++)
            #pragma unroll
            for (int nt = 0; nt < 8; nt++)
                s[mf][nt][0] = s[mf][nt][1] = s[mf][nt][2] = s[mf][nt][3] = 0.f;
        #pragma unroll
        for (int kf = 0; kf < 2; kf++) {
            #pragma unroll
            for (int nt = 0; nt < 8; nt++) {
                const int row = (nt * 8 + g) * KST2;
                unsigned b0h = Ksh[row + 8 * kf + t];
                unsigned b1h = Ksh[row + 8 * kf + t + 4];
                unsigned b0l = Ksl[row + 8 * kf + t];
                unsigned b1l = Ksl[row + 8 * kf + t + 4];
                mma_bf16(s[0][nt], qh[0][kf], b0h, b1h);
                mma_bf16(s[0][nt], qh[0][kf], b0l, b1l);
                mma_bf16(s[0][nt], ql[0][kf], b0h, b1h);
                mma_bf16(s[1][nt], qh[1][kf], b0h, b1h);
                mma_bf16(s[1][nt], qh[1][kf], b0l, b1l);
                mma_bf16(s[1][nt], ql[1][kf], b0h, b1h);
            }
        }

        // ---- online softmax per m-frag ----
        #pragma unroll
        for (int mf = 0; mf < 2; mf++) {
            float tA = -CUDART_INF_F, tB = -CUDART_INF_F;
            #pragma unroll
            for (int nt = 0; nt < 8; nt++) {
                tA = fmaxf(tA, fmaxf(s[mf][nt][0], s[mf][nt][1]));
                tB = fmaxf(tB, fmaxf(s[mf][nt][2], s[mf][nt][3]));
            }
            tA = rmax4(tA); tB = rmax4(tB);
            float mAn = fmaxf(mst[mf][0], tA), mBn = fmaxf(mst[mf][1], tB);
            float aA = __expf(mst[mf][0] - mAn), aB = __expf(mst[mf][1] - mBn);
            float sumA = 0.f, sumB = 0.f;
            #pragma unroll
            for (int nt = 0; nt < 8; nt++) {
                s[mf][nt][0] = __expf(s[mf][nt][0] - mAn);
                s[mf][nt][1] = __expf(s[mf][nt][1] - mAn);
                s[mf][nt][2] = __expf(s[mf][nt][2] - mBn);
                s[mf][nt][3] = __expf(s[mf][nt][3] - mBn);
                sumA += s[mf][nt][0] + s[mf][nt][1];
                sumB += s[mf][nt][2] + s[mf][nt][3];
            }
            sumA = rsum4(sumA); sumB = rsum4(sumB);
            lst[mf][0] = lst[mf][0] * aA + sumA;
            lst[mf][1] = lst[mf][1] * aB + sumB;
            mst[mf][0] = mAn; mst[mf][1] = mBn;
            #pragma unroll
            for (int nt = 0; nt < 4; nt++) {
                o[mf][nt][0] *= aA; o[mf][nt][1] *= aA;
                o[mf][nt][2] *= aB; o[mf][nt][3] *= aB;
            }
        }

        // ---- O += P V: P A-fragments straight from S C-fragments ----
        #pragma unroll
        for (int kf = 0; kf < 4; kf++) {
            unsigned pah[2][4], pal[2][4];
            #pragma unroll
            for (int mf = 0; mf < 2; mf++) {
                split2_bf16(s[mf][2*kf][0],   s[mf][2*kf][1],   pah[mf][0], pal[mf][0]);
                split2_bf16(s[mf][2*kf][2],   s[mf][2*kf][3],   pah[mf][1], pal[mf][1]);
                split2_bf16(s[mf][2*kf+1][0], s[mf][2*kf+1][1], pah[mf][2], pal[mf][2]);
                split2_bf16(s[mf][2*kf+1][2], s[mf][2*kf+1][3], pah[mf][3], pal[mf][3]);
            }
            #pragma unroll
            for (int nt = 0; nt < 4; nt++) {
                const int row = (nt * 8 + g) * VST2;
                unsigned b0h = Vsh[row + 8 * kf + t];
                unsigned b1h = Vsh[row + 8 * kf + t + 4];
                unsigned b0l = Vsl[row + 8 * kf + t];
                unsigned b1l = Vsl[row + 8 * kf + t + 4];
                mma_bf16(o[0][nt], pah[0], b0h, b1h);
                mma_bf16(o[0][nt], pah[0], b0l, b1l);
                mma_bf16(o[0][nt], pal[0], b0h, b1h);
                mma_bf16(o[1][nt], pah[1], b0h, b1h);
                mma_bf16(o[1][nt], pah[1], b0l, b1l);
                mma_bf16(o[1][nt], pal[1], b0h, b1h);
            }
        }
    }

    // ---- epilogue: normalize + store pre-split O planes ----
    #pragma unroll
    for (int mf = 0; mf < 2; mf++) {
        const float iA = 1.0f / lst[mf][0], iB = 1.0f / lst[mf][1];
        const int rA = qrow0 + mf * 16, rB = rA + 8;
        #pragma unroll
        for (int nt = 0; nt < 4; nt++) {
            int d0 = nt * 8 + 2 * t;
            size_t rowb = (size_t)((bh * 32 + d0) >> 1) * NPIX;
            unsigned h, l;
            split2_bf16(o[mf][nt][0] * iA, o[mf][nt][1] * iA, h, l);
            g_oh[rowb + rA] = h;
            g_ol[rowb + rA] = l;
            split2_bf16(o[mf][nt][2] * iB, o[mf][nt][3] * iB, h, l);
            g_oh[rowb + rB] = h;
            g_ol[rowb + rB] = l;
        }
    }
}

// ---------------------------------------------------------------------------
// Kernel 3: output projection, bf16x3 + bias.  X loads are pure uint copies
// of the pre-split O planes.
// ---------------------------------------------------------------------------
__global__ void __launch_bounds__(128) proj_mma_kernel(const float* __restrict__ w,
                                                       const float* __restrict__ bias,
                                                       float* __restrict__ out)
{
    __shared__ __align__(16) unsigned Wh2[128 * WST2], Wl2[128 * WST2];
    __shared__ __align__(16) unsigned Xh2[8 * NST2],  Xl2[8 * NST2];

    const int b  = blockIdx.z;
    const int ob = blockIdx.y * 128;
    const int nb = blockIdx.x * 64;
    const int tid  = threadIdx.x;
    const int warp = tid >> 5;
    const int lane = tid & 31;
    const int g = lane >> 2, t = lane & 3;

    float acc[2][8][4] = {};

    for (int kb = 0; kb < HID; kb += 16) {
        __syncthreads();
        #pragma unroll
        for (int j = 0; j < 4; j++) {
            int i = tid + j * 128;
            int o = i >> 2, k4 = (i & 3) * 4;
            float4 wv = *(const float4*)&w[(ob + o) * HID + kb + k4];
            unsigned h0, l0, h1, l1;
            split2_bf16(wv.x, wv.y, h0, l0);
            split2_bf16(wv.z, wv.w, h1, l1);
            *(uint2*)&Wh2[o * WST2 + k4 / 2] = make_uint2(h0, h1);
            *(uint2*)&Wl2[o * WST2 + k4 / 2] = make_uint2(l0, l1);
        }
        #pragma unroll
        for (int s = 0; s < 4; s++) {
            int i = tid + s * 128;
            int n = i & 63, k2 = i >> 6;
            size_t src = (size_t)(b * 64 + kb / 2 + k2) * NPIX + nb + n;
            Xh2[k2 * NST2 + n] = g_oh[src];
            Xl2[k2 * NST2 + n] = g_ol[src];
        }
        __syncthreads();

        unsigned ah[2][4], al[2][4];
        #pragma unroll
        for (int mf = 0; mf < 2; mf++) {
            const int wo = warp * 32 + mf * 16;
            ah[mf][0] = Wh2[(wo + g)     * WST2 + t];     al[mf][0] = Wl2[(wo + g)     * WST2 + t];
            ah[mf][1] = Wh2[(wo + 8 + g) * WST2 + t];     al[mf][1] = Wl2[(wo + 8 + g) * WST2 + t];
            ah[mf][2] = Wh2[(wo + g)     * WST2 + t + 4]; al[mf][2] = Wl2[(wo + g)     * WST2 + t + 4];
            ah[mf][3] = Wh2[(wo + 8 + g) * WST2 + t + 4]; al[mf][3] = Wl2[(wo + 8 + g) * WST2 + t + 4];
        }
        #pragma unroll
        for (int nt = 0; nt < 8; nt++) {
            unsigned b0h = Xh2[t       * NST2 + nt * 8 + g];
            unsigned b1h = Xh2[(t + 4) * NST2 + nt * 8 + g];
            unsigned b0l = Xl2[t       * NST2 + nt * 8 + g];
            unsigned b1l = Xl2[(t + 4) * NST2 + nt * 8 + g];
            mma_bf16(acc[0][nt], ah[0], b0h, b1h);
            mma_bf16(acc[0][nt], ah[0], b0l, b1l);
            mma_bf16(acc[0][nt], al[0], b0h, b1h);
            mma_bf16(acc[1][nt], ah[1], b0h, b1h);
            mma_bf16(acc[1][nt], ah[1], b0l, b1l);
            mma_bf16(acc[1][nt], al[1], b0h, b1h);
        }
    }

    #pragma unroll
    for (int mf = 0; mf < 2; mf++) {
        #pragma unroll
        for (int r = 0; r < 2; r++) {
            int o = ob + warp * 32 + mf * 16 + r * 8 + g;
            float bv = bias[o];
            float* row = out + (size_t)(b * CIN + o) * NPIX + nb + 2 * t;
            #pragma unroll
            for (int nt = 0; nt < 8; nt++)
                *(float2*)&row[nt * 8] = make_float2(acc[mf][nt][2 * r] + bv,
                                                     acc[mf][nt][2 * r + 1] + bv);
        }
    }
}

// ---------------------------------------------------------------------------
extern "C" void kernel_launch(void* const* d_in, const int* in_sizes, int n_in,
                              void* d_out, int out_size)
{
    const float* x     = (const float*)d_in[0];  // [8,256,48,48]
    const float* w_qkv = (const float*)d_in[1];  // [384,256]
    const float* w_out = (const float*)d_in[2];  // [256,128]
    const float* b_out = (const float*)d_in[3];  // [256]
    float* out = (float*)d_out;                  // [8,256,48,48]

    {
        dim3 grid(NPIX / 64, (3 * HID) / 128, BATCH);  // 36 x 3 x 8
        qkv_mma_kernel<<<grid, 128>>>(x, w_qkv);
    }
    {
        dim3 grid(NPIX / QTILE, BATCH * NHEADS);        // 18 x 32
        attn_mma_kernel<<<grid, 128>>>();
    }
    {
        dim3 grid(NPIX / 64, CIN / 128, BATCH);         // 36 x 2 x 8
        proj_mma_kernel<<<grid, 128>>>(w_out, b_out, out);
    }
}

// round 17
// speedup vs baseline: 1.0576x; 1.0576x over previous
#include <cuda_runtime.h>
#include <cuda_bf16.h>
#include <math_constants.h>

// Problem constants
#define NPIX 2304          // 48*48
#define NPIX2 1152         // NPIX/2
#define CIN  256
#define HID  128
#define NHEADS 4
#define DHEAD 32
#define BATCH 8
#define QSCALE 0.17677669529663687f   // 1/sqrt(32)

// Pre-split bf16 planes (hi/lo):
//   Q,K : uint [bh][n][16]      (uint = bf16 pair (2i,2i+1) of dims)
//   V   : uint [bh*32+d][n2]    (uint = key pair (2n,2n+1) at dim d)
//   O   : uint [b*64+c2][n]     (uint = dim pair (2c,2c+1) at pixel n)
//   W   : uint [o][k2]          (uint = k pair; qkv q-rows pre-scaled)
__device__ unsigned g_qh[BATCH * NHEADS * NPIX * 16];
__device__ unsigned g_ql[BATCH * NHEADS * NPIX * 16];
__device__ unsigned g_kh[BATCH * NHEADS * NPIX * 16];
__device__ unsigned g_kl[BATCH * NHEADS * NPIX * 16];
__device__ unsigned g_vh[BATCH * NHEADS * 32 * NPIX2];
__device__ unsigned g_vl[BATCH * NHEADS * 32 * NPIX2];
__device__ unsigned g_oh[BATCH * 64 * NPIX];
__device__ unsigned g_ol[BATCH * 64 * NPIX];
__device__ unsigned g_wqh[384 * 128];   // w_qkv planes: [384][128] uints (256 k)
__device__ unsigned g_wql[384 * 128];
__device__ unsigned g_woh[256 * 64];    // w_out planes: [256][64] uints (128 k)
__device__ unsigned g_wol[256 * 64];

// ---------------------------------------------------------------------------
// Helpers
// ---------------------------------------------------------------------------
__device__ __forceinline__ unsigned pack_bf16(float lo, float hi)
{
    unsigned r;
    asm("cvt.rn.bf16x2.f32 %0, %1, %2;" : "=r"(r) : "f"(hi), "f"(lo));
    return r;
}

__device__ __forceinline__ void split2_bf16(float v0, float v1,
                                            unsigned& h, unsigned& l)
{
    h = pack_bf16(v0, v1);
    float h0 = __uint_as_float(h << 16);
    float h1 = __uint_as_float(h & 0xffff0000u);
    l = pack_bf16(v0 - h0, v1 - h1);
}

__device__ __forceinline__ void mma_bf16(float d[4], const unsigned a[4],
                                         unsigned b0, unsigned b1)
{
    asm volatile(
        "mma.sync.aligned.m16n8k16.row.col.f32.bf16.bf16.f32 "
        "{%0,%1,%2,%3}, {%4,%5,%6,%7}, {%8,%9}, {%0,%1,%2,%3};\n"
        : "+f"(d[0]), "+f"(d[1]), "+f"(d[2]), "+f"(d[3])
        : "r"(a[0]), "r"(a[1]), "r"(a[2]), "r"(a[3]), "r"(b0), "r"(b1));
}

__device__ __forceinline__ float rmax4(float v) {
    v = fmaxf(v, __shfl_xor_sync(0xffffffffu, v, 1));
    v = fmaxf(v, __shfl_xor_sync(0xffffffffu, v, 2));
    return v;
}
__device__ __forceinline__ float rsum4(float v) {
    v += __shfl_xor_sync(0xffffffffu, v, 1);
    v += __shfl_xor_sync(0xffffffffu, v, 2);
    return v;
}

__device__ __forceinline__ void cpasync16(void* dst, const void* src)
{
    unsigned sa = (unsigned)__cvta_generic_to_shared(dst);
    asm volatile("cp.async.ca.shared.global [%0], [%1], 16;\n" :: "r"(sa), "l"(src));
}
#define CP_COMMIT() asm volatile("cp.async.commit_group;\n" ::: "memory")
#define CP_WAIT1()  asm volatile("cp.async.wait_group 1;\n" ::: "memory")
#define CP_WAIT0()  asm volatile("cp.async.wait_group 0;\n" ::: "memory")

#define WST2 12
#define NST2 72

// ---------------------------------------------------------------------------
// Kernel 0: pre-split weights (runs once per launch, ~40K elements)
// ---------------------------------------------------------------------------
__global__ void prep_w_kernel(const float* __restrict__ wqkv,
                              const float* __restrict__ wout)
{
    int i = blockIdx.x * 256 + threadIdx.x;
    if (i < 384 * 128) {                       // w_qkv: 384 rows x 128 uints
        int o = i >> 7, q = i & 127;
        float2 v = *(const float2*)&wqkv[o * CIN + 2 * q];
        float m = (o < 128) ? QSCALE : 1.0f;   // fold q-scale into weights
        unsigned h, l;
        split2_bf16(v.x * m, v.y * m, h, l);
        g_wqh[i] = h; g_wql[i] = l;
    } else {
        int j = i - 384 * 128;                 // w_out: 256 rows x 64 uints
        if (j < 256 * 64) {
            int o = j >> 6, q = j & 63;
            float2 v = *(const float2*)&wout[o * HID + 2 * q];
            unsigned h, l;
            split2_bf16(v.x, v.y, h, l);
            g_woh[j] = h; g_wol[j] = l;
        }
    }
}

// ---------------------------------------------------------------------------
// Kernel 1: QKV projection, bf16x3 mma.  W pre-split; epilogue pairs d-dims
// via shfl+byte_perm for uint Q/K plane stores.
// ---------------------------------------------------------------------------
__global__ void __launch_bounds__(128) qkv_mma_kernel(const float* __restrict__ x)
{
    __shared__ __align__(16) unsigned Wh2[128 * WST2], Wl2[128 * WST2];
    __shared__ __align__(16) unsigned Xh2[8 * NST2],  Xl2[8 * NST2];

    const int b  = blockIdx.z;
    const int ob = blockIdx.y * 128;
    const int nb = blockIdx.x * 64;
    const int tid  = threadIdx.x;
    const int warp = tid >> 5;
    const int lane = tid & 31;
    const int g = lane >> 2, t = lane & 3;

    const float* xb = x + (size_t)b * CIN * NPIX;

    float acc[2][8][4] = {};

    for (int kb = 0; kb < CIN; kb += 16) {
        __syncthreads();
        // W tile: pure uint4 copies of pre-split planes
        #pragma unroll
        for (int s = 0; s < 4; s++) {
            int i = tid + s * 128;
            int p = i >> 8, r = i & 255;
            int o = r >> 1, c = r & 1;
            const unsigned* src = (p ? g_wql : g_wqh) + (size_t)(ob + o) * 128 + kb / 2 + c * 4;
            unsigned* dst = (p ? Wl2 : Wh2) + o * WST2 + c * 4;
            *(uint4*)dst = *(const uint4*)src;
        }
        // X tile: 16k x 64n, transposed split -> [k2][n]
        #pragma unroll
        for (int s = 0; s < 4; s++) {
            int i = tid + s * 128;
            int n = i & 63, k2 = i >> 6;
            const float* base = &xb[(size_t)(kb + 2 * k2) * NPIX + nb + n];
            unsigned h, l;
            split2_bf16(base[0], base[NPIX], h, l);
            Xh2[k2 * NST2 + n] = h;
            Xl2[k2 * NST2 + n] = l;
        }
        __syncthreads();

        unsigned ah[2][4], al[2][4];
        #pragma unroll
        for (int mf = 0; mf < 2; mf++) {
            const int wo = warp * 32 + mf * 16;
            ah[mf][0] = Wh2[(wo + g)     * WST2 + t];     al[mf][0] = Wl2[(wo + g)     * WST2 + t];
            ah[mf][1] = Wh2[(wo + 8 + g) * WST2 + t];     al[mf][1] = Wl2[(wo + 8 + g) * WST2 + t];
            ah[mf][2] = Wh2[(wo + g)     * WST2 + t + 4]; al[mf][2] = Wl2[(wo + g)     * WST2 + t + 4];
            ah[mf][3] = Wh2[(wo + 8 + g) * WST2 + t + 4]; al[mf][3] = Wl2[(wo + 8 + g) * WST2 + t + 4];
        }
        #pragma unroll
        for (int nt = 0; nt < 8; nt++) {
            unsigned b0h = Xh2[t       * NST2 + nt * 8 + g];
            unsigned b1h = Xh2[(t + 4) * NST2 + nt * 8 + g];
            unsigned b0l = Xl2[t       * NST2 + nt * 8 + g];
            unsigned b1l = Xl2[(t + 4) * NST2 + nt * 8 + g];
            mma_bf16(acc[0][nt], ah[0], b0h, b1h);
            mma_bf16(acc[0][nt], ah[0], b0l, b1l);
            mma_bf16(acc[0][nt], al[0], b0h, b1h);
            mma_bf16(acc[1][nt], ah[1], b0h, b1h);
            mma_bf16(acc[1][nt], ah[1], b0l, b1l);
            mma_bf16(acc[1][nt], al[1], b0h, b1h);
        }
    }

    // Epilogue.  sec uniform per block.
    const int sec = ob >> 7;   // 0=q, 1=k, 2=v
    #pragma unroll
    for (int mf = 0; mf < 2; mf++) {
        #pragma unroll
        for (int r = 0; r < 2; r++) {
            int o  = ob + warp * 32 + mf * 16 + r * 8 + g;
            int oc = o & 127;
            int bh = b * NHEADS + (oc >> 5);
            int d  = oc & 31;
            if (sec == 2) {
                unsigned* vh = g_vh + (size_t)(bh * 32 + d) * NPIX2;
                unsigned* vl = g_vl + (size_t)(bh * 32 + d) * NPIX2;
                #pragma unroll
                for (int nt = 0; nt < 8; nt++) {
                    int n0 = nb + nt * 8 + 2 * t;
                    unsigned h, l;
                    split2_bf16(acc[mf][nt][2 * r], acc[mf][nt][2 * r + 1], h, l);
                    vh[n0 / 2] = h;
                    vl[n0 / 2] = l;
                }
            } else {
                // Q/K: pair dims d (even g) with d+1 (odd g) via shfl+byte_perm
                unsigned* dh = ((sec == 0) ? g_qh : g_kh) + (size_t)bh * NPIX * 16;
                unsigned* dl = ((sec == 0) ? g_ql : g_kl) + (size_t)bh * NPIX * 16;
                #pragma unroll
                for (int nt = 0; nt < 8; nt++) {
                    int n0 = nb + nt * 8 + 2 * t;
                    unsigned h, l;
                    split2_bf16(acc[mf][nt][2 * r], acc[mf][nt][2 * r + 1], h, l);
                    unsigned ph = __shfl_xor_sync(0xffffffffu, h, 4);
                    unsigned pl = __shfl_xor_sync(0xffffffffu, l, 4);
                    if (!(g & 1)) {
                        size_t i0 = (size_t)n0 * 16 + (d >> 1);
                        dh[i0]      = __byte_perm(h, ph, 0x5410);
                        dh[i0 + 16] = __byte_perm(h, ph, 0x7632);
                        dl[i0]      = __byte_perm(l, pl, 0x5410);
                        dl[i0 + 16] = __byte_perm(l, pl, 0x7632);
                    }
                }
            }
        }
    }
}

// ---------------------------------------------------------------------------
// Kernel 2: flash attention, bf16x3, cp.async double-buffered K/V tiles.
// QTILE=128 (warp = 32 q), KTILE=64.
// ---------------------------------------------------------------------------
#define KTILE 64
#define QTILE 128
#define KST2  20    // 80B row: 16B-aligned for cp.async
#define VST2  36    // 144B row: 16B-aligned
#define KBUF  (64 * KST2)
#define VBUF  (32 * VST2)

__global__ void __launch_bounds__(128) attn_mma_kernel()
{
    __shared__ __align__(16) unsigned Ksh[2 * KBUF], Ksl[2 * KBUF];
    __shared__ __align__(16) unsigned Vsh[2 * VBUF], Vsl[2 * VBUF];

    const int bh    = blockIdx.y;
    const int qbase = blockIdx.x * QTILE;
    const int tid   = threadIdx.x;
    const int warp  = tid >> 5;
    const int lane  = tid & 31;
    const int g     = lane >> 2;
    const int t     = lane & 3;

    const unsigned* qhp = g_qh + (size_t)bh * NPIX * 16;
    const unsigned* qlp = g_ql + (size_t)bh * NPIX * 16;
    const unsigned* khp = g_kh + (size_t)bh * NPIX * 16;
    const unsigned* klp = g_kl + (size_t)bh * NPIX * 16;
    const unsigned* vhp = g_vh + (size_t)bh * 32 * NPIX2;
    const unsigned* vlp = g_vl + (size_t)bh * 32 * NPIX2;

    // Tile loader: pure cp.async copies (8 x 16B per thread)
    auto load_tile = [&](int kb, int bi) {
        unsigned* Kd[2] = { Ksh + bi * KBUF, Ksl + bi * KBUF };
        unsigned* Vd[2] = { Vsh + bi * VBUF, Vsl + bi * VBUF };
        const unsigned* Ks[2] = { khp, klp };
        const unsigned* Vs[2] = { vhp, vlp };
        #pragma unroll
        for (int s = 0; s < 4; s++) {
            int i = tid + s * 128;
            {   // K: 64 rows x 4 uint4-chunks x 2 planes
                int p = i >> 8, r = i & 255;
                int j = r >> 2, c = r & 3;
                cpasync16(Kd[p] + j * KST2 + c * 4,
                          Ks[p] + (size_t)(kb + j) * 16 + c * 4);
            }
            {   // V: 32 rows x 8 uint4-chunks x 2 planes
                int p = i >> 8, r = i & 255;
                int j = r >> 3, c = r & 7;
                cpasync16(Vd[p] + j * VST2 + c * 4,
                          Vs[p] + (size_t)j * NPIX2 + kb / 2 + c * 4);
            }
        }
    };

    // Kick off first tile before Q-fragment loads (overlap)
    load_tile(0, 0);
    CP_COMMIT();

    // Resident Q A-fragments: direct uint reads
    unsigned qh[2][2][4], ql[2][2][4];
    const int qrow0 = qbase + warp * 32 + g;
    #pragma unroll
    for (int mf = 0; mf < 2; mf++) {
        const int rA = qrow0 + mf * 16, rB = rA + 8;
        #pragma unroll
        for (int kf = 0; kf < 2; kf++) {
            qh[mf][kf][0] = qhp[(size_t)rA * 16 + 8 * kf + t];
            qh[mf][kf][1] = qhp[(size_t)rB * 16 + 8 * kf + t];
            qh[mf][kf][2] = qhp[(size_t)rA * 16 + 8 * kf + t + 4];
            qh[mf][kf][3] = qhp[(size_t)rB * 16 + 8 * kf + t + 4];
            ql[mf][kf][0] = qlp[(size_t)rA * 16 + 8 * kf + t];
            ql[mf][kf][1] = qlp[(size_t)rB * 16 + 8 * kf + t];
            ql[mf][kf][2] = qlp[(size_t)rA * 16 + 8 * kf + t + 4];
            ql[mf][kf][3] = qlp[(size_t)rB * 16 + 8 * kf + t + 4];
        }
    }

    float o[2][4][4] = {};
    float mst[2][2], lst[2][2];
    #pragma unroll
    for (int mf = 0; mf < 2; mf++) {
        mst[mf][0] = -CUDART_INF_F; mst[mf][1] = -CUDART_INF_F;
        lst[mf][0] = 0.f;           lst[mf][1] = 0.f;
    }

    const int NT = NPIX / KTILE;   // 36
    for (int it = 0; it < NT; it++) {
        const int bi = it & 1;
        if (it + 1 < NT) {
            load_tile((it + 1) * KTILE, bi ^ 1);
            CP_COMMIT();
            CP_WAIT1();
        } else {
            CP_WAIT0();
        }
        __syncthreads();

        const unsigned* Kh = Ksh + bi * KBUF;
        const unsigned* Kl = Ksl + bi * KBUF;
        const unsigned* Vh = Vsh + bi * VBUF;
        const unsigned* Vl = Vsl + bi * VBUF;

        // ---- S = Q K^T (32 x 64 per warp), bf16x3 ----
        float s[2][8][4];
        #pragma unroll
        for (int mf = 0; mf < 2; mf++)
            #pragma unroll
            for (int nt = 0; nt < 8; nt++)
                s[mf][nt][0] = s[mf][nt][1] = s[mf][nt][2] = s[mf][nt][3] = 0.f;
        #pragma unroll
        for (int kf = 0; kf < 2; kf++) {
            #pragma unroll
            for (int nt = 0; nt < 8; nt++) {
                const int row = (nt * 8 + g) * KST2;
                unsigned b0h = Kh[row + 8 * kf + t];
                unsigned b1h = Kh[row + 8 * kf + t + 4];
                unsigned b0l = Kl[row + 8 * kf + t];
                unsigned b1l = Kl[row + 8 * kf + t + 4];
                mma_bf16(s[0][nt], qh[0][kf], b0h, b1h);
                mma_bf16(s[0][nt], qh[0][kf], b0l, b1l);
                mma_bf16(s[0][nt], ql[0][kf], b0h, b1h);
                mma_bf16(s[1][nt], qh[1][kf], b0h, b1h);
                mma_bf16(s[1][nt], qh[1][kf], b0l, b1l);
                mma_bf16(s[1][nt], ql[1][kf], b0h, b1h);
            }
        }

        // ---- online softmax per m-frag ----
        #pragma unroll
        for (int mf = 0; mf < 2; mf++) {
            float tA = -CUDART_INF_F, tB = -CUDART_INF_F;
            #pragma unroll
            for (int nt = 0; nt < 8; nt++) {
                tA = fmaxf(tA, fmaxf(s[mf][nt][0], s[mf][nt][1]));
                tB = fmaxf(tB, fmaxf(s[mf][nt][2], s[mf][nt][3]));
            }
            tA = rmax4(tA); tB = rmax4(tB);
            float mAn = fmaxf(mst[mf][0], tA), mBn = fmaxf(mst[mf][1], tB);
            float aA = __expf(mst[mf][0] - mAn), aB = __expf(mst[mf][1] - mBn);
            float sumA = 0.f, sumB = 0.f;
            #pragma unroll
            for (int nt = 0; nt < 8; nt++) {
                s[mf][nt][0] = __expf(s[mf][nt][0] - mAn);
                s[mf][nt][1] = __expf(s[mf][nt][1] - mAn);
                s[mf][nt][2] = __expf(s[mf][nt][2] - mBn);
                s[mf][nt][3] = __expf(s[mf][nt][3] - mBn);
                sumA += s[mf][nt][0] + s[mf][nt][1];
                sumB += s[mf][nt][2] + s[mf][nt][3];
            }
            sumA = rsum4(sumA); sumB = rsum4(sumB);
            lst[mf][0] = lst[mf][0] * aA + sumA;
            lst[mf][1] = lst[mf][1] * aB + sumB;
            mst[mf][0] = mAn; mst[mf][1] = mBn;
            #pragma unroll
            for (int nt = 0; nt < 4; nt++) {
                o[mf][nt][0] *= aA; o[mf][nt][1] *= aA;
                o[mf][nt][2] *= aB; o[mf][nt][3] *= aB;
            }
        }

        // ---- O += P V ----
        #pragma unroll
        for (int kf = 0; kf < 4; kf++) {
            unsigned pah[2][4], pal[2][4];
            #pragma unroll
            for (int mf = 0; mf < 2; mf++) {
                split2_bf16(s[mf][2*kf][0],   s[mf][2*kf][1],   pah[mf][0], pal[mf][0]);
                split2_bf16(s[mf][2*kf][2],   s[mf][2*kf][3],   pah[mf][1], pal[mf][1]);
                split2_bf16(s[mf][2*kf+1][0], s[mf][2*kf+1][1], pah[mf][2], pal[mf][2]);
                split2_bf16(s[mf][2*kf+1][2], s[mf][2*kf+1][3], pah[mf][3], pal[mf][3]);
            }
            #pragma unroll
            for (int nt = 0; nt < 4; nt++) {
                const int row = (nt * 8 + g) * VST2;
                unsigned b0h = Vh[row + 8 * kf + t];
                unsigned b1h = Vh[row + 8 * kf + t + 4];
                unsigned b0l = Vl[row + 8 * kf + t];
                unsigned b1l = Vl[row + 8 * kf + t + 4];
                mma_bf16(o[0][nt], pah[0], b0h, b1h);
                mma_bf16(o[0][nt], pah[0], b0l, b1l);
                mma_bf16(o[0][nt], pal[0], b0h, b1h);
                mma_bf16(o[1][nt], pah[1], b0h, b1h);
                mma_bf16(o[1][nt], pah[1], b0l, b1l);
                mma_bf16(o[1][nt], pal[1], b0h, b1h);
            }
        }
        __syncthreads();
    }

    // ---- epilogue: normalize + store pre-split O planes ----
    #pragma unroll
    for (int mf = 0; mf < 2; mf++) {
        const float iA = 1.0f / lst[mf][0], iB = 1.0f / lst[mf][1];
        const int rA = qrow0 + mf * 16, rB = rA + 8;
        #pragma unroll
        for (int nt = 0; nt < 4; nt++) {
            int d0 = nt * 8 + 2 * t;
            size_t rowb = (size_t)((bh * 32 + d0) >> 1) * NPIX;
            unsigned h, l;
            split2_bf16(o[mf][nt][0] * iA, o[mf][nt][1] * iA, h, l);
            g_oh[rowb + rA] = h;
            g_ol[rowb + rA] = l;
            split2_bf16(o[mf][nt][2] * iB, o[mf][nt][3] * iB, h, l);
            g_oh[rowb + rB] = h;
            g_ol[rowb + rB] = l;
        }
    }
}

// ---------------------------------------------------------------------------
// Kernel 3: output projection, bf16x3 + bias.  W and X loads pure copies.
// ---------------------------------------------------------------------------
__global__ void __launch_bounds__(128) proj_mma_kernel(const float* __restrict__ bias,
                                                       float* __restrict__ out)
{
    __shared__ __align__(16) unsigned Wh2[128 * WST2], Wl2[128 * WST2];
    __shared__ __align__(16) unsigned Xh2[8 * NST2],  Xl2[8 * NST2];

    const int b  = blockIdx.z;
    const int ob = blockIdx.y * 128;
    const int nb = blockIdx.x * 64;
    const int tid  = threadIdx.x;
    const int warp = tid >> 5;
    const int lane = tid & 31;
    const int g = lane >> 2, t = lane & 3;

    float acc[2][8][4] = {};

    for (int kb = 0; kb < HID; kb += 16) {
        __syncthreads();
        #pragma unroll
        for (int s = 0; s < 4; s++) {
            int i = tid + s * 128;
            int p = i >> 8, r = i & 255;
            int o = r >> 1, c = r & 1;
            const unsigned* src = (p ? g_wol : g_woh) + (size_t)(ob + o) * 64 + kb / 2 + c * 4;
            unsigned* dst = (p ? Wl2 : Wh2) + o * WST2 + c * 4;
            *(uint4*)dst = *(const uint4*)src;
        }
        #pragma unroll
        for (int s = 0; s < 4; s++) {
            int i = tid + s * 128;
            int n = i & 63, k2 = i >> 6;
            size_t src = (size_t)(b * 64 + kb / 2 + k2) * NPIX + nb + n;
            Xh2[k2 * NST2 + n] = g_oh[src];
            Xl2[k2 * NST2 + n] = g_ol[src];
        }
        __syncthreads();

        unsigned ah[2][4], al[2][4];
        #pragma unroll
        for (int mf = 0; mf < 2; mf++) {
            const int wo = warp * 32 + mf * 16;
            ah[mf][0] = Wh2[(wo + g)     * WST2 + t];     al[mf][0] = Wl2[(wo + g)     * WST2 + t];
            ah[mf][1] = Wh2[(wo + 8 + g) * WST2 + t];     al[mf][1] = Wl2[(wo + 8 + g) * WST2 + t];
            ah[mf][2] = Wh2[(wo + g)     * WST2 + t + 4]; al[mf][2] = Wl2[(wo + g)     * WST2 + t + 4];
            ah[mf][3] = Wh2[(wo + 8 + g) * WST2 + t + 4]; al[mf][3] = Wl2[(wo + 8 + g) * WST2 + t + 4];
        }
        #pragma unroll
        for (int nt = 0; nt < 8; nt++) {
            unsigned b0h = Xh2[t       * NST2 + nt * 8 + g];
            unsigned b1h = Xh2[(t + 4) * NST2 + nt * 8 + g];
            unsigned b0l = Xl2[t       * NST2 + nt * 8 + g];
            unsigned b1l = Xl2[(t + 4) * NST2 + nt * 8 + g];
            mma_bf16(acc[0][nt], ah[0], b0h, b1h);
            mma_bf16(acc[0][nt], ah[0], b0l, b1l);
            mma_bf16(acc[0][nt], al[0], b0h, b1h);
            mma_bf16(acc[1][nt], ah[1], b0h, b1h);
            mma_bf16(acc[1][nt], ah[1], b0l, b1l);
            mma_bf16(acc[1][nt], al[1], b0h, b1h);
        }
    }

    #pragma unroll
    for (int mf = 0; mf < 2; mf++) {
        #pragma unroll
        for (int r = 0; r < 2; r++) {
            int o = ob + warp * 32 + mf * 16 + r * 8 + g;
            float bv = bias[o];
            float* row = out + (size_t)(b * CIN + o) * NPIX + nb + 2 * t;
            #pragma unroll
            for (int nt = 0; nt < 8; nt++)
                *(float2*)&row[nt * 8] = make_float2(acc[mf][nt][2 * r] + bv,
                                                     acc[mf][nt][2 * r + 1] + bv);
        }
    }
}

// ---------------------------------------------------------------------------
extern "C" void kernel_launch(void* const* d_in, const int* in_sizes, int n_in,
                              void* d_out, int out_size)
{
    const float* x     = (const float*)d_in[0];  // [8,256,48,48]
    const float* w_qkv = (const float*)d_in[1];  // [384,256]
    const float* w_out = (const float*)d_in[2];  // [256,128]
    const float* b_out = (const float*)d_in[3];  // [256]
    float* out = (float*)d_out;                  // [8,256,48,48]

    prep_w_kernel<<<256, 256>>>(w_qkv, w_out);   // 384*128 + 256*64 = 65536 items
    {
        dim3 grid(NPIX / 64, (3 * HID) / 128, BATCH);  // 36 x 3 x 8
        qkv_mma_kernel<<<grid, 128>>>(x);
    }
    {
        dim3 grid(NPIX / QTILE, BATCH * NHEADS);        // 18 x 32
        attn_mma_kernel<<<grid, 128>>>();
    }
    {
        dim3 grid(NPIX / 64, CIN / 128, BATCH);         // 36 x 2 x 8
        proj_mma_kernel<<<grid, 128>>>(b_out, out);
    }
}